// round 15
// baseline (speedup 1.0000x reference)
#include <cuda_runtime.h>
#include <cuda_fp16.h>
#include <cstdint>
#include <cstddef>

#define BB 8
#define NN 4096
#define EE 2048
#define CC 128

// Edge features (f16) produced by fused s1, consumed by s3
__device__ __half g_E[BB * EE * CC];

#define BM 128
#define BK 32
#define NTH 256
#define LDH 36     // halfs per row in As/Bs (pad 4) -> conflict-free LDS.32 frags
#define LDZ 136    // halfs per row in zsm/wsm (K=128 + pad 8)

__device__ __forceinline__ uint32_t pk(float x, float y) {
    __half2 h = __floats2half2_rn(x, y);
    return *reinterpret_cast<uint32_t*>(&h);
}
__device__ __forceinline__ uint32_t pkh(__half x, __half y) {
    __half2 h = __halves2half2(x, y);
    return *reinterpret_cast<uint32_t*>(&h);
}

__device__ __forceinline__ void mma16(float& d0, float& d1, float& d2, float& d3,
                                      uint32_t a0, uint32_t a1, uint32_t a2, uint32_t a3,
                                      uint32_t b0, uint32_t b1) {
    asm volatile(
        "mma.sync.aligned.m16n8k16.row.col.f32.f16.f16.f32 "
        "{%0,%1,%2,%3},{%4,%5,%6,%7},{%8,%9},{%0,%1,%2,%3};"
        : "+f"(d0), "+f"(d1), "+f"(d2), "+f"(d3)
        : "r"(a0), "r"(a1), "r"(a2), "r"(a3), "r"(b0), "r"(b1));
}

// ===========================================================================
// S1 (+fused projection):
//   D1[e][c] = sum_n H[n][e] * X[n][c]   (f16 mma, f32 accumulate)
//   se[e]    = sum_n H[n][e]             (accumulated in staging registers)
//   E[e][c'] = se>0 ? (D1/se) @ W + b : 0   -> g_E (f16)
// ===========================================================================
__global__ void __launch_bounds__(NTH, 2)
s1_kernel(const float* __restrict__ H, const float* __restrict__ X,
          const float* __restrict__ Wm, const float* __restrict__ bias) {
    const int b = blockIdx.y, e0 = blockIdx.x * BM;
    extern __shared__ __half sm[];
    __half* As = sm;                    // 2 bufs * 128*36 halfs  (A = H^T [e][n])
    __half* Bs = sm + 2 * BM * LDH;     // 2 bufs * 128*36 halfs  (B = [c][n])
    __half* zsm = sm;                   // epilogue overlay: 128*136 halfs
    __half* wsm = sm + BM * LDZ;        // 128*136 halfs
    __shared__ float s_part[2][BM];
    __shared__ float s_rs[BM], s_inv[BM], s_b[CC];

    const int tid = threadIdx.x, lane = tid & 31, wid = tid >> 5;
    const int g = lane >> 2, tg = lane & 3;
    const int wm = (wid >> 2) * 64, wn = (wid & 3) * 32;   // warp tile 64x32
    const int eloc = tid & 127, t7 = tid >> 7;

    if (tid < CC) s_b[tid] = bias[tid];

    const float* Hb = H + (size_t)b * NN * EE + e0 + eloc;
    const float* Xb = X + (size_t)b * NN * CC + eloc;

    float acc[4][4][4];
#pragma unroll
    for (int i = 0; i < 4; i++)
#pragma unroll
        for (int j = 0; j < 4; j++)
#pragma unroll
            for (int k = 0; k < 4; k++) acc[i][j][k] = 0.f;
    float rs = 0.f;
    uint32_t aPk[8], bPk[8];

    auto PF = [&](int n0) {
#pragma unroll
        for (int i = 0; i < 4; i++) {
            const int kq = t7 + 2 * i;
            const float* hp = Hb + (size_t)(n0 + 4 * kq) * EE;
            float h0 = hp[0], h1 = hp[EE], h2 = hp[2 * EE], h3 = hp[3 * EE];
            rs += (h0 + h1) + (h2 + h3);
            aPk[2 * i] = pk(h0, h1);
            aPk[2 * i + 1] = pk(h2, h3);
            const float* xp = Xb + (size_t)(n0 + 4 * kq) * CC;
            bPk[2 * i] = pk(xp[0], xp[CC]);
            bPk[2 * i + 1] = pk(xp[2 * CC], xp[3 * CC]);
        }
    };
    auto STS = [&](int buf) {
        __half* Ad = As + buf * BM * LDH;
        __half* Bd = Bs + buf * BM * LDH;
#pragma unroll
        for (int i = 0; i < 4; i++) {
            const int kq = t7 + 2 * i;
            *reinterpret_cast<uint2*>(Ad + eloc * LDH + kq * 4) =
                make_uint2(aPk[2 * i], aPk[2 * i + 1]);
            *reinterpret_cast<uint2*>(Bd + eloc * LDH + kq * 4) =
                make_uint2(bPk[2 * i], bPk[2 * i + 1]);
        }
    };
    auto COMPUTE = [&](int buf) {
        const __half* Ad = As + buf * BM * LDH;
        const __half* Bd = Bs + buf * BM * LDH;
#pragma unroll
        for (int kk = 0; kk < BK; kk += 16) {
            uint32_t af[4][4], bf[4][2];
#pragma unroll
            for (int mt = 0; mt < 4; mt++) {
                const __half* ap = Ad + (wm + mt * 16 + g) * LDH + kk + 2 * tg;
                af[mt][0] = *(const uint32_t*)ap;
                af[mt][1] = *(const uint32_t*)(ap + 8 * LDH);
                af[mt][2] = *(const uint32_t*)(ap + 8);
                af[mt][3] = *(const uint32_t*)(ap + 8 * LDH + 8);
            }
#pragma unroll
            for (int nt = 0; nt < 4; nt++) {
                const __half* bp = Bd + (wn + nt * 8 + g) * LDH + kk + 2 * tg;
                bf[nt][0] = *(const uint32_t*)bp;
                bf[nt][1] = *(const uint32_t*)(bp + 8);
            }
#pragma unroll
            for (int mt = 0; mt < 4; mt++)
#pragma unroll
                for (int nt = 0; nt < 4; nt++)
                    mma16(acc[mt][nt][0], acc[mt][nt][1], acc[mt][nt][2], acc[mt][nt][3],
                          af[mt][0], af[mt][1], af[mt][2], af[mt][3],
                          bf[nt][0], bf[nt][1]);
        }
    };

    PF(0); STS(0); __syncthreads();
    int buf = 0;
    const int KT = NN / BK;   // 128
    for (int kt = 0; kt < KT; kt++) {
        if (kt + 1 < KT) PF((kt + 1) * BK);
        COMPUTE(buf);
        if (kt + 1 < KT) {
            STS(buf ^ 1);
            __syncthreads();
            buf ^= 1;
        }
    }

    // se reduce (2 partials per e)
    s_part[t7][eloc] = rs;
    __syncthreads();
    if (tid < BM) {
        float s = s_part[0][tid] + s_part[1][tid];
        s_rs[tid] = s;
        s_inv[tid] = (s > 0.f) ? (1.f / s) : 0.f;
    }
    __syncthreads();   // also: main buffers dead -> overlay safe

    // ---- zhat -> zsm[e][c] f16;  W^T -> wsm[c'][c] f16 ----
#pragma unroll
    for (int mt = 0; mt < 4; mt++) {
        const int r0 = wm + mt * 16 + g;
        const float i0 = s_inv[r0], i1 = s_inv[r0 + 8];
#pragma unroll
        for (int nt = 0; nt < 4; nt++) {
            const int c = wn + nt * 8 + 2 * tg;
            *(uint32_t*)(zsm + r0 * LDZ + c) = pk(acc[mt][nt][0] * i0, acc[mt][nt][1] * i0);
            *(uint32_t*)(zsm + (r0 + 8) * LDZ + c) = pk(acc[mt][nt][2] * i1, acc[mt][nt][3] * i1);
        }
    }
    {
        const int cp = tid & 127;
#pragma unroll
        for (int i = 0; i < 16; i++) {
            const int kq = t7 + 2 * i;
            const float* wp = Wm + (size_t)(4 * kq) * CC + cp;
            *reinterpret_cast<uint2*>(wsm + cp * LDZ + kq * 4) =
                make_uint2(pk(wp[0], wp[CC]), pk(wp[2 * CC], wp[3 * CC]));
        }
    }
    __syncthreads();

    // ---- projection: E[e][c'] = zhat @ W  (K=128, f16 mma) ----
    float ac2[4][4][4];
#pragma unroll
    for (int i = 0; i < 4; i++)
#pragma unroll
        for (int j = 0; j < 4; j++)
#pragma unroll
            for (int k = 0; k < 4; k++) ac2[i][j][k] = 0.f;
#pragma unroll
    for (int kk = 0; kk < CC; kk += 16) {
        uint32_t af[4][4], bf[4][2];
#pragma unroll
        for (int mt = 0; mt < 4; mt++) {
            const __half* ap = zsm + (wm + mt * 16 + g) * LDZ + kk + 2 * tg;
            af[mt][0] = *(const uint32_t*)ap;
            af[mt][1] = *(const uint32_t*)(ap + 8 * LDZ);
            af[mt][2] = *(const uint32_t*)(ap + 8);
            af[mt][3] = *(const uint32_t*)(ap + 8 * LDZ + 8);
        }
#pragma unroll
        for (int nt = 0; nt < 4; nt++) {
            const __half* bp = wsm + (wn + nt * 8 + g) * LDZ + kk + 2 * tg;
            bf[nt][0] = *(const uint32_t*)bp;
            bf[nt][1] = *(const uint32_t*)(bp + 8);
        }
#pragma unroll
        for (int mt = 0; mt < 4; mt++)
#pragma unroll
            for (int nt = 0; nt < 4; nt++)
                mma16(ac2[mt][nt][0], ac2[mt][nt][1], ac2[mt][nt][2], ac2[mt][nt][3],
                      af[mt][0], af[mt][1], af[mt][2], af[mt][3],
                      bf[nt][0], bf[nt][1]);
    }

    // ---- bias + guard + store E (f16) ----
#pragma unroll
    for (int mt = 0; mt < 4; mt++) {
        const int r0 = wm + mt * 16 + g;
        const bool ok0 = s_rs[r0] > 0.f;
        const bool ok1 = s_rs[r0 + 8] > 0.f;
        __half* ep0 = g_E + ((size_t)(b * EE + e0 + r0)) * CC;
        __half* ep1 = ep0 + (size_t)8 * CC;
#pragma unroll
        for (int nt = 0; nt < 4; nt++) {
            const int c = wn + nt * 8 + 2 * tg;
            const float b0v = s_b[c], b1v = s_b[c + 1];
            *(uint32_t*)(ep0 + c) = pk(ok0 ? ac2[mt][nt][0] + b0v : 0.f,
                                       ok0 ? ac2[mt][nt][1] + b1v : 0.f);
            *(uint32_t*)(ep1 + c) = pk(ok1 ? ac2[mt][nt][2] + b0v : 0.f,
                                       ok1 ? ac2[mt][nt][3] + b1v : 0.f);
        }
    }
}

// ===========================================================================
// S3: v[n][c] = (sum_e H[n][e] * E[e][c]) / sv[n]   (sv from A staging)
// ===========================================================================
__global__ void __launch_bounds__(NTH, 2)
s3_kernel(const float* __restrict__ H, float* __restrict__ out) {
    const int b = blockIdx.y, n0 = blockIdx.x * BM;
    extern __shared__ __half sm[];
    __half* As = sm;                    // A = H [n][e]
    __half* Bs = sm + 2 * BM * LDH;     // B = E^T [c][e]
    __shared__ float s_part[BM][8];
    __shared__ float s_inv[BM];

    const int tid = threadIdx.x, lane = tid & 31, wid = tid >> 5;
    const int g = lane >> 2, tg = lane & 3;
    const int wm = (wid >> 2) * 64, wn = (wid & 3) * 32;
    const int cloc = tid & 127, t7 = tid >> 7;
    const int am = tid >> 3, ak4 = tid & 7;

    const float* Hb = H + (size_t)b * NN * EE;
    const __half* Eb = g_E + (size_t)b * EE * CC;

    float acc[4][4][4];
#pragma unroll
    for (int i = 0; i < 4; i++)
#pragma unroll
        for (int j = 0; j < 4; j++)
#pragma unroll
            for (int k = 0; k < 4; k++) acc[i][j][k] = 0.f;
    float rsv[4] = {0.f, 0.f, 0.f, 0.f};
    uint32_t aPk[8], bPk[8];

    auto PF = [&](int es) {
#pragma unroll
        for (int i = 0; i < 4; i++) {
            const int m = am + 32 * i;
            const float4 f = *reinterpret_cast<const float4*>(
                Hb + (size_t)(n0 + m) * EE + es + 4 * ak4);
            rsv[i] += (f.x + f.y) + (f.z + f.w);
            aPk[2 * i] = pk(f.x, f.y);
            aPk[2 * i + 1] = pk(f.z, f.w);
            const int kq = t7 + 2 * i;
            const __half* ep = Eb + (size_t)(es + 4 * kq) * CC + cloc;
            bPk[2 * i] = pkh(ep[0], ep[CC]);
            bPk[2 * i + 1] = pkh(ep[2 * CC], ep[3 * CC]);
        }
    };
    auto STS = [&](int buf) {
        __half* Ad = As + buf * BM * LDH;
        __half* Bd = Bs + buf * BM * LDH;
#pragma unroll
        for (int i = 0; i < 4; i++) {
            const int m = am + 32 * i;
            *reinterpret_cast<uint2*>(Ad + m * LDH + ak4 * 4) =
                make_uint2(aPk[2 * i], aPk[2 * i + 1]);
            const int kq = t7 + 2 * i;
            *reinterpret_cast<uint2*>(Bd + cloc * LDH + kq * 4) =
                make_uint2(bPk[2 * i], bPk[2 * i + 1]);
        }
    };
    auto COMPUTE = [&](int buf) {
        const __half* Ad = As + buf * BM * LDH;
        const __half* Bd = Bs + buf * BM * LDH;
#pragma unroll
        for (int kk = 0; kk < BK; kk += 16) {
            uint32_t af[4][4], bf[4][2];
#pragma unroll
            for (int mt = 0; mt < 4; mt++) {
                const __half* ap = Ad + (wm + mt * 16 + g) * LDH + kk + 2 * tg;
                af[mt][0] = *(const uint32_t*)ap;
                af[mt][1] = *(const uint32_t*)(ap + 8 * LDH);
                af[mt][2] = *(const uint32_t*)(ap + 8);
                af[mt][3] = *(const uint32_t*)(ap + 8 * LDH + 8);
            }
#pragma unroll
            for (int nt = 0; nt < 4; nt++) {
                const __half* bp = Bd + (wn + nt * 8 + g) * LDH + kk + 2 * tg;
                bf[nt][0] = *(const uint32_t*)bp;
                bf[nt][1] = *(const uint32_t*)(bp + 8);
            }
#pragma unroll
            for (int mt = 0; mt < 4; mt++)
#pragma unroll
                for (int nt = 0; nt < 4; nt++)
                    mma16(acc[mt][nt][0], acc[mt][nt][1], acc[mt][nt][2], acc[mt][nt][3],
                          af[mt][0], af[mt][1], af[mt][2], af[mt][3],
                          bf[nt][0], bf[nt][1]);
        }
    };

    PF(0); STS(0); __syncthreads();
    int buf = 0;
    const int KT = EE / BK;   // 64
    for (int kt = 0; kt < KT; kt++) {
        if (kt + 1 < KT) PF((kt + 1) * BK);
        COMPUTE(buf);
        if (kt + 1 < KT) {
            STS(buf ^ 1);
            __syncthreads();
            buf ^= 1;
        }
    }

    // sv reduce (8 partials per n-row)
#pragma unroll
    for (int i = 0; i < 4; i++) s_part[am + 32 * i][ak4] = rsv[i];
    __syncthreads();
    if (tid < BM) {
        const float* p = s_part[tid];
        float s = ((p[0] + p[1]) + (p[2] + p[3])) + ((p[4] + p[5]) + (p[6] + p[7]));
        s_inv[tid] = (s > 0.f) ? (1.f / s) : 0.f;
    }
    __syncthreads();

#pragma unroll
    for (int mt = 0; mt < 4; mt++) {
        const int r0 = wm + mt * 16 + g;
        const float i0 = s_inv[r0], i1 = s_inv[r0 + 8];
        float* op0 = out + (size_t)(b * NN + n0 + r0) * CC;
        float* op1 = op0 + (size_t)8 * CC;
#pragma unroll
        for (int nt = 0; nt < 4; nt++) {
            const int c = wn + nt * 8 + 2 * tg;
            float2 v0 = make_float2(acc[mt][nt][0] * i0, acc[mt][nt][1] * i0);
            float2 v1 = make_float2(acc[mt][nt][2] * i1, acc[mt][nt][3] * i1);
            *reinterpret_cast<float2*>(op0 + c) = v0;
            *reinterpret_cast<float2*>(op1 + c) = v1;
        }
    }
}

// ===========================================================================
extern "C" void kernel_launch(void* const* d_in, const int* in_sizes, int n_in,
                              void* d_out, int out_size) {
    const float* X = nullptr;
    const float* H = nullptr;
    const float* W = nullptr;
    const float* bias = nullptr;
    for (int i = 0; i < n_in; i++) {
        if (in_sizes[i] == BB * NN * CC)      X = (const float*)d_in[i];
        else if (in_sizes[i] == BB * NN * EE) H = (const float*)d_in[i];
        else if (in_sizes[i] == CC * CC)      W = (const float*)d_in[i];
        else if (in_sizes[i] == CC)           bias = (const float*)d_in[i];
    }
    float* out = (float*)d_out;

    const int main_bytes = 2 * 2 * BM * LDH * (int)sizeof(__half);   // 36864
    const int epi_bytes  = 2 * BM * LDZ * (int)sizeof(__half);       // 69632
    const int smem1 = (main_bytes > epi_bytes) ? main_bytes : epi_bytes;
    const int smem3 = main_bytes;

    cudaFuncSetAttribute(s1_kernel, cudaFuncAttributeMaxDynamicSharedMemorySize, smem1);
    cudaFuncSetAttribute(s3_kernel, cudaFuncAttributeMaxDynamicSharedMemorySize, smem3);

    s1_kernel<<<dim3(EE / BM, BB), NTH, smem1>>>(H, X, W, bias);
    s3_kernel<<<dim3(NN / BM, BB), NTH, smem3>>>(H, out);
}

// round 16
// speedup vs baseline: 1.3182x; 1.3182x over previous
#include <cuda_runtime.h>
#include <cuda_fp16.h>
#include <cstdint>
#include <cstddef>

#define BB 8
#define NN 4096
#define EE 2048
#define CC 128

// Edge features (f16), 16B-aligned for uint4 access in s3
__device__ __align__(16) __half g_E[BB * EE * CC];

#define BM 128
#define BK 32
#define NTH 256
#define LKM 136          // halfs per row for [k][x] tiles (128 + 8 pad) -> 272B rows (17x16B, odd)
#define LKM_B 272
#define LDA3 72          // halfs per row for s3 A [m][k] tiles (32 + pad) -> 144B rows (9x16B, odd)
#define LDA3_B 144
#define LDZ 136          // s1 epilogue row halfs

#define KMSZ_B (32 * LKM_B)        // 8704 bytes: one [32][LKM] f16 buffer
#define ASZ3_B (BM * LDA3_B)       // 18432 bytes: one s3 A buffer

__device__ __forceinline__ uint32_t smem_u32(const void* p) {
    uint32_t a;
    asm("{ .reg .u64 t; cvta.to.shared.u64 t, %1; cvt.u32.u64 %0, t; }" : "=r"(a) : "l"(p));
    return a;
}
__device__ __forceinline__ uint32_t pk(float x, float y) {
    __half2 h = __floats2half2_rn(x, y);
    return *reinterpret_cast<uint32_t*>(&h);
}

__device__ __forceinline__ void ldsm4(uint32_t* r, uint32_t a) {
    asm volatile("ldmatrix.sync.aligned.m8n8.x4.shared.b16 {%0,%1,%2,%3}, [%4];"
                 : "=r"(r[0]), "=r"(r[1]), "=r"(r[2]), "=r"(r[3]) : "r"(a));
}
__device__ __forceinline__ void ldsm4t(uint32_t* r, uint32_t a) {
    asm volatile("ldmatrix.sync.aligned.m8n8.x4.trans.shared.b16 {%0,%1,%2,%3}, [%4];"
                 : "=r"(r[0]), "=r"(r[1]), "=r"(r[2]), "=r"(r[3]) : "r"(a));
}

__device__ __forceinline__ void mma16(float& d0, float& d1, float& d2, float& d3,
                                      uint32_t a0, uint32_t a1, uint32_t a2, uint32_t a3,
                                      uint32_t b0, uint32_t b1) {
    asm volatile(
        "mma.sync.aligned.m16n8k16.row.col.f32.f16.f16.f32 "
        "{%0,%1,%2,%3},{%4,%5,%6,%7},{%8,%9},{%0,%1,%2,%3};"
        : "+f"(d0), "+f"(d1), "+f"(d2), "+f"(d3)
        : "r"(a0), "r"(a1), "r"(a2), "r"(a3), "r"(b0), "r"(b1));
}

// ===========================================================================
// S1 (+fused projection):
//   D1[e][c] = sum_n H[n][e] * X[n][c]   (A=H^T via ldmatrix.trans on [n][e] tiles)
//   se[e]    = sum_n H[n][e]             (per-thread per-e accumulators in staging)
//   E[e][c'] = se>0 ? (D1/se) @ W + b : 0   -> g_E (f16)
// ===========================================================================
__global__ void __launch_bounds__(NTH, 2)
s1_kernel(const float* __restrict__ H, const float* __restrict__ X,
          const float* __restrict__ Wm, const float* __restrict__ bias) {
    const int b = blockIdx.y, e0 = blockIdx.x * BM;
    extern __shared__ __half sm[];
    __half* As = sm;                       // 2 bufs [32][LKM]  (H tile, [n][e])
    __half* Bs = sm + 2 * 32 * LKM;        // 2 bufs [32][LKM]  (X tile, [n][c])
    __half* zsm = sm;                      // epilogue overlay [128][LDZ]
    __half* wsm = sm + BM * LDZ;           // [128][LDZ]
    __shared__ float s_part[16][BM];
    __shared__ float s_rs[BM], s_inv[BM], s_b[CC];

    const int tid = threadIdx.x, lane = tid & 31, wid = tid >> 5;
    const int g = lane >> 2, tg = lane & 3;
    const int wm = (wid >> 2) * 64, wn = (wid & 3) * 32;   // 2x4 warps, 64x32 tiles
    const int ec = tid & 15, rg = tid >> 4;                 // staging map
    const int t7 = tid >> 7;

    if (tid < CC) s_b[tid] = bias[tid];

    const uint32_t uA = smem_u32(As), uB = smem_u32(Bs);
    // ldmatrix lane offsets (bytes)
    const uint32_t aoff = (uint32_t)(((lane & 7) + ((lane >> 4) & 1) * 8) * LKM_B
                                     + ((lane >> 3) & 1) * 16);
    const uint32_t boff = (uint32_t)((lane & 7) * LKM_B + (lane >> 3) * 16);

    const float* Hb = H + (size_t)b * NN * EE + e0 + ec * 8;
    const float* Xb = X + (size_t)b * NN * CC + ec * 8;

    float acc[4][4][4];
#pragma unroll
    for (int i = 0; i < 4; i++)
#pragma unroll
        for (int j = 0; j < 4; j++)
#pragma unroll
            for (int k = 0; k < 4; k++) acc[i][j][k] = 0.f;
    float sacc[8];
#pragma unroll
    for (int i = 0; i < 8; i++) sacc[i] = 0.f;

    uint4 ha[2], xa[2];

    auto PF = [&](int n0) {
#pragma unroll
        for (int rr = 0; rr < 2; rr++) {
            const int n = n0 + rg * 2 + rr;
            const float* hp = Hb + (size_t)n * EE;
            float4 h0 = *reinterpret_cast<const float4*>(hp);
            float4 h1 = *reinterpret_cast<const float4*>(hp + 4);
            sacc[0] += h0.x; sacc[1] += h0.y; sacc[2] += h0.z; sacc[3] += h0.w;
            sacc[4] += h1.x; sacc[5] += h1.y; sacc[6] += h1.z; sacc[7] += h1.w;
            ha[rr] = make_uint4(pk(h0.x, h0.y), pk(h0.z, h0.w),
                                pk(h1.x, h1.y), pk(h1.z, h1.w));
            const float* xp = Xb + (size_t)n * CC;
            float4 x0 = *reinterpret_cast<const float4*>(xp);
            float4 x1 = *reinterpret_cast<const float4*>(xp + 4);
            xa[rr] = make_uint4(pk(x0.x, x0.y), pk(x0.z, x0.w),
                                pk(x1.x, x1.y), pk(x1.z, x1.w));
        }
    };
    auto STS = [&](int buf) {
        __half* Ad = As + buf * 32 * LKM;
        __half* Bd = Bs + buf * 32 * LKM;
#pragma unroll
        for (int rr = 0; rr < 2; rr++) {
            const int n = rg * 2 + rr;
            *reinterpret_cast<uint4*>(Ad + n * LKM + ec * 8) = ha[rr];
            *reinterpret_cast<uint4*>(Bd + n * LKM + ec * 8) = xa[rr];
        }
    };
    auto COMPUTE = [&](int buf) {
        const uint32_t aB = uA + buf * KMSZ_B + (uint32_t)(wm * 2) + aoff;
        const uint32_t bB = uB + buf * KMSZ_B + (uint32_t)(wn * 2) + boff;
#pragma unroll
        for (int kk = 0; kk < BK; kk += 16) {
            uint32_t af[4][4], b0[4], b1[4];
#pragma unroll
            for (int mt = 0; mt < 4; mt++)
                ldsm4t(af[mt], aB + kk * LKM_B + mt * 32);
            ldsm4t(b0, bB + kk * LKM_B);
            ldsm4t(b1, bB + (kk + 8) * LKM_B);
#pragma unroll
            for (int mt = 0; mt < 4; mt++)
#pragma unroll
                for (int nt = 0; nt < 4; nt++)
                    mma16(acc[mt][nt][0], acc[mt][nt][1], acc[mt][nt][2], acc[mt][nt][3],
                          af[mt][0], af[mt][1], af[mt][2], af[mt][3],
                          b0[nt], b1[nt]);
        }
    };

    PF(0); STS(0); __syncthreads();
    int buf = 0;
    const int KT = NN / BK;   // 128
    for (int kt = 0; kt < KT; kt++) {
        if (kt + 1 < KT) PF((kt + 1) * BK);
        COMPUTE(buf);
        if (kt + 1 < KT) {
            STS(buf ^ 1);
            __syncthreads();
            buf ^= 1;
        }
    }

    // se reduce: 16 rowgroup partials per e
#pragma unroll
    for (int j = 0; j < 8; j++) s_part[rg][ec * 8 + j] = sacc[j];
    __syncthreads();
    if (tid < BM) {
        float s = 0.f;
#pragma unroll
        for (int r = 0; r < 16; r++) s += s_part[r][tid];
        s_rs[tid] = s;
        s_inv[tid] = (s > 0.f) ? (1.f / s) : 0.f;
    }
    __syncthreads();   // main buffers dead -> overlay safe

    // ---- zhat -> zsm[e][c] f16;  W -> wsm[c'][k=c] f16 ----
#pragma unroll
    for (int mt = 0; mt < 4; mt++) {
        const int r0 = wm + mt * 16 + g;
        const float i0 = s_inv[r0], i1 = s_inv[r0 + 8];
#pragma unroll
        for (int nt = 0; nt < 4; nt++) {
            const int c = wn + nt * 8 + 2 * tg;
            *(uint32_t*)(zsm + r0 * LDZ + c) = pk(acc[mt][nt][0] * i0, acc[mt][nt][1] * i0);
            *(uint32_t*)(zsm + (r0 + 8) * LDZ + c) = pk(acc[mt][nt][2] * i1, acc[mt][nt][3] * i1);
        }
    }
    {
        const int cp = tid & 127;
#pragma unroll
        for (int i = 0; i < 16; i++) {
            const int kq = t7 + 2 * i;
            const float* wp = Wm + (size_t)(4 * kq) * CC + cp;
            *reinterpret_cast<uint2*>(wsm + cp * LDZ + kq * 4) =
                make_uint2(pk(wp[0], wp[CC]), pk(wp[2 * CC], wp[3 * CC]));
        }
    }
    __syncthreads();

    // ---- projection: E[e][c'] = zhat @ W  (K=128) ----
    float ac2[4][4][4];
#pragma unroll
    for (int i = 0; i < 4; i++)
#pragma unroll
        for (int j = 0; j < 4; j++)
#pragma unroll
            for (int k = 0; k < 4; k++) ac2[i][j][k] = 0.f;
#pragma unroll
    for (int kk = 0; kk < CC; kk += 16) {
        uint32_t af[4][4], bf[4][2];
#pragma unroll
        for (int mt = 0; mt < 4; mt++) {
            const __half* ap = zsm + (wm + mt * 16 + g) * LDZ + kk + 2 * tg;
            af[mt][0] = *(const uint32_t*)ap;
            af[mt][1] = *(const uint32_t*)(ap + 8 * LDZ);
            af[mt][2] = *(const uint32_t*)(ap + 8);
            af[mt][3] = *(const uint32_t*)(ap + 8 * LDZ + 8);
        }
#pragma unroll
        for (int nt = 0; nt < 4; nt++) {
            const __half* bp = wsm + (wn + nt * 8 + g) * LDZ + kk + 2 * tg;
            bf[nt][0] = *(const uint32_t*)bp;
            bf[nt][1] = *(const uint32_t*)(bp + 8);
        }
#pragma unroll
        for (int mt = 0; mt < 4; mt++)
#pragma unroll
            for (int nt = 0; nt < 4; nt++)
                mma16(ac2[mt][nt][0], ac2[mt][nt][1], ac2[mt][nt][2], ac2[mt][nt][3],
                      af[mt][0], af[mt][1], af[mt][2], af[mt][3],
                      bf[nt][0], bf[nt][1]);
    }

    // ---- bias + guard + store E (f16) ----
#pragma unroll
    for (int mt = 0; mt < 4; mt++) {
        const int r0 = wm + mt * 16 + g;
        const bool ok0 = s_rs[r0] > 0.f;
        const bool ok1 = s_rs[r0 + 8] > 0.f;
        __half* ep0 = g_E + ((size_t)(b * EE + e0 + r0)) * CC;
        __half* ep1 = ep0 + (size_t)8 * CC;
#pragma unroll
        for (int nt = 0; nt < 4; nt++) {
            const int c = wn + nt * 8 + 2 * tg;
            const float b0v = s_b[c], b1v = s_b[c + 1];
            *(uint32_t*)(ep0 + c) = pk(ok0 ? ac2[mt][nt][0] + b0v : 0.f,
                                       ok0 ? ac2[mt][nt][1] + b1v : 0.f);
            *(uint32_t*)(ep1 + c) = pk(ok1 ? ac2[mt][nt][2] + b0v : 0.f,
                                       ok1 ? ac2[mt][nt][3] + b1v : 0.f);
        }
    }
}

// ===========================================================================
// S3: v[n][c] = (sum_e H[n][e] * E[e][c]) / sv[n]
//   A = H [n][e] row-major (ldmatrix non-trans), B = E [e][c] (ldmatrix.trans)
// ===========================================================================
__global__ void __launch_bounds__(NTH, 2)
s3_kernel(const float* __restrict__ H, float* __restrict__ out) {
    const int b = blockIdx.y, n0 = blockIdx.x * BM;
    extern __shared__ __half sm[];
    __half* As = sm;                        // 2 bufs [128][LDA3]  (H tile [n][e])
    __half* Bs = sm + 2 * BM * LDA3;        // 2 bufs [32][LKM]    (E tile [e][c])
    __shared__ float s_part[BM][2];
    __shared__ float s_inv[BM];

    const int tid = threadIdx.x, lane = tid & 31, wid = tid >> 5;
    const int g = lane >> 2, tg = lane & 3;
    const int wm = (wid >> 2) * 64, wn = (wid & 3) * 32;
    const int mrow = tid >> 1, hh = tid & 1;      // A staging: 2 threads/row
    const int uu = tid & 15, rw = tid >> 4;       // B staging

    const uint32_t uA = smem_u32(As), uB = smem_u32(Bs);
    const uint32_t aoffA = (uint32_t)(((lane & 7) + ((lane >> 3) & 1) * 8) * LDA3_B
                                      + ((lane >> 4) & 1) * 16);
    const uint32_t boff = (uint32_t)((lane & 7) * LKM_B + (lane >> 3) * 16);

    const float* Hb = H + (size_t)b * NN * EE;
    const __half* Eb = g_E + (size_t)b * EE * CC;

    float acc[4][4][4];
#pragma unroll
    for (int i = 0; i < 4; i++)
#pragma unroll
        for (int j = 0; j < 4; j++)
#pragma unroll
            for (int k = 0; k < 4; k++) acc[i][j][k] = 0.f;
    float rsv = 0.f;

    uint4 pa[2], eb[2];

    auto PF = [&](int es) {
        const float* hp = Hb + (size_t)(n0 + mrow) * EE + es + hh * 16;
        float4 f0 = *reinterpret_cast<const float4*>(hp);
        float4 f1 = *reinterpret_cast<const float4*>(hp + 4);
        float4 f2 = *reinterpret_cast<const float4*>(hp + 8);
        float4 f3 = *reinterpret_cast<const float4*>(hp + 12);
        rsv += ((f0.x + f0.y) + (f0.z + f0.w)) + ((f1.x + f1.y) + (f1.z + f1.w))
             + ((f2.x + f2.y) + (f2.z + f2.w)) + ((f3.x + f3.y) + (f3.z + f3.w));
        pa[0] = make_uint4(pk(f0.x, f0.y), pk(f0.z, f0.w), pk(f1.x, f1.y), pk(f1.z, f1.w));
        pa[1] = make_uint4(pk(f2.x, f2.y), pk(f2.z, f2.w), pk(f3.x, f3.y), pk(f3.z, f3.w));
#pragma unroll
        for (int rr = 0; rr < 2; rr++) {
            const int row = rw + rr * 16;
            eb[rr] = *reinterpret_cast<const uint4*>(Eb + (size_t)(es + row) * CC + uu * 8);
        }
    };
    auto STS = [&](int buf) {
        __half* Ad = As + buf * BM * LDA3;
        __half* Bd = Bs + buf * 32 * LKM;
        *reinterpret_cast<uint4*>(Ad + mrow * LDA3 + hh * 16) = pa[0];
        *reinterpret_cast<uint4*>(Ad + mrow * LDA3 + hh * 16 + 8) = pa[1];
#pragma unroll
        for (int rr = 0; rr < 2; rr++) {
            const int row = rw + rr * 16;
            *reinterpret_cast<uint4*>(Bd + row * LKM + uu * 8) = eb[rr];
        }
    };
    auto COMPUTE = [&](int buf) {
        const uint32_t aB = uA + buf * ASZ3_B + (uint32_t)(wm * LDA3_B) + aoffA;
        const uint32_t bB = uB + buf * KMSZ_B + (uint32_t)(wn * 2) + boff;
#pragma unroll
        for (int kk = 0; kk < BK; kk += 16) {
            uint32_t af[4][4], b0[4], b1[4];
#pragma unroll
            for (int mt = 0; mt < 4; mt++)
                ldsm4(af[mt], aB + mt * 16 * LDA3_B + kk * 2);
            ldsm4t(b0, bB + kk * LKM_B);
            ldsm4t(b1, bB + (kk + 8) * LKM_B);
#pragma unroll
            for (int mt = 0; mt < 4; mt++)
#pragma unroll
                for (int nt = 0; nt < 4; nt++)
                    mma16(acc[mt][nt][0], acc[mt][nt][1], acc[mt][nt][2], acc[mt][nt][3],
                          af[mt][0], af[mt][1], af[mt][2], af[mt][3],
                          b0[nt], b1[nt]);
        }
    };

    PF(0); STS(0); __syncthreads();
    int buf = 0;
    const int KT = EE / BK;   // 64
    for (int kt = 0; kt < KT; kt++) {
        if (kt + 1 < KT) PF((kt + 1) * BK);
        COMPUTE(buf);
        if (kt + 1 < KT) {
            STS(buf ^ 1);
            __syncthreads();
            buf ^= 1;
        }
    }

    s_part[mrow][hh] = rsv;
    __syncthreads();
    if (tid < BM) {
        float s = s_part[tid][0] + s_part[tid][1];
        s_inv[tid] = (s > 0.f) ? (1.f / s) : 0.f;
    }
    __syncthreads();

#pragma unroll
    for (int mt = 0; mt < 4; mt++) {
        const int r0 = wm + mt * 16 + g;
        const float i0 = s_inv[r0], i1 = s_inv[r0 + 8];
        float* op0 = out + (size_t)(b * NN + n0 + r0) * CC;
        float* op1 = op0 + (size_t)8 * CC;
#pragma unroll
        for (int nt = 0; nt < 4; nt++) {
            const int c = wn + nt * 8 + 2 * tg;
            *reinterpret_cast<float2*>(op0 + c) =
                make_float2(acc[mt][nt][0] * i0, acc[mt][nt][1] * i0);
            *reinterpret_cast<float2*>(op1 + c) =
                make_float2(acc[mt][nt][2] * i1, acc[mt][nt][3] * i1);
        }
    }
}

// ===========================================================================
extern "C" void kernel_launch(void* const* d_in, const int* in_sizes, int n_in,
                              void* d_out, int out_size) {
    const float* X = nullptr;
    const float* H = nullptr;
    const float* W = nullptr;
    const float* bias = nullptr;
    for (int i = 0; i < n_in; i++) {
        if (in_sizes[i] == BB * NN * CC)      X = (const float*)d_in[i];
        else if (in_sizes[i] == BB * NN * EE) H = (const float*)d_in[i];
        else if (in_sizes[i] == CC * CC)      W = (const float*)d_in[i];
        else if (in_sizes[i] == CC)           bias = (const float*)d_in[i];
    }
    float* out = (float*)d_out;

    const int s1_main = 2 * KMSZ_B * 2;                         // 34816
    const int s1_epi  = 2 * BM * LDZ * (int)sizeof(__half);     // 69632
    const int smem1 = (s1_main > s1_epi) ? s1_main : s1_epi;
    const int smem3 = 2 * ASZ3_B + 2 * KMSZ_B;                  // 54272

    cudaFuncSetAttribute(s1_kernel, cudaFuncAttributeMaxDynamicSharedMemorySize, smem1);
    cudaFuncSetAttribute(s3_kernel, cudaFuncAttributeMaxDynamicSharedMemorySize, smem3);

    s1_kernel<<<dim3(EE / BM, BB), NTH, smem1>>>(H, X, W, bias);
    s3_kernel<<<dim3(NN / BM, BB), NTH, smem3>>>(H, out);
}

// round 17
// speedup vs baseline: 1.4325x; 1.0867x over previous
#include <cuda_runtime.h>
#include <cuda_fp16.h>
#include <cstdint>
#include <cstddef>

#define BB 8
#define NN 4096
#define EE 2048
#define CC 128

// f16 caches (written by cvt/s1, no cudaMalloc allowed)
__device__ __align__(16) __half g_Hh[(size_t)BB * NN * EE];   // H as f16, [b][n][e]
__device__ __align__(16) __half g_Xh[(size_t)BB * NN * CC];   // X as f16, [b][n][c]
__device__ __align__(16) __half g_E [(size_t)BB * EE * CC];   // edge feats f16, [b][e][c]

#define BM 128
#define BK 32
#define NTH 256
#define NSTG 3
#define LKM 136          // halfs/row for [k][128] tiles -> 272B rows (17x16B, odd)
#define LKM_B 272
#define LDA3 72          // halfs/row for s3 A [m][32] tiles -> 144B rows (9x16B, odd)
#define LDA3_B 144
#define LDZ 136          // s1 epilogue row halfs
#define KMSZ_B (32 * LKM_B)        // 8704 B
#define ASZ3_B (BM * LDA3_B)       // 18432 B

__device__ __forceinline__ uint32_t smem_u32(const void* p) {
    uint32_t a;
    asm("{ .reg .u64 t; cvta.to.shared.u64 t, %1; cvt.u32.u64 %0, t; }" : "=r"(a) : "l"(p));
    return a;
}
__device__ __forceinline__ uint32_t pk(float x, float y) {
    __half2 h = __floats2half2_rn(x, y);
    return *reinterpret_cast<uint32_t*>(&h);
}
__device__ __forceinline__ void cpa16(uint32_t dst, const void* src) {
    asm volatile("cp.async.cg.shared.global [%0], [%1], 16;" :: "r"(dst), "l"(src));
}
#define CP_COMMIT() asm volatile("cp.async.commit_group;" ::: "memory")
#define CP_WAIT1()  asm volatile("cp.async.wait_group 1;" ::: "memory")

__device__ __forceinline__ void ldsm4(uint32_t* r, uint32_t a) {
    asm volatile("ldmatrix.sync.aligned.m8n8.x4.shared.b16 {%0,%1,%2,%3}, [%4];"
                 : "=r"(r[0]), "=r"(r[1]), "=r"(r[2]), "=r"(r[3]) : "r"(a));
}
__device__ __forceinline__ void ldsm4t(uint32_t* r, uint32_t a) {
    asm volatile("ldmatrix.sync.aligned.m8n8.x4.trans.shared.b16 {%0,%1,%2,%3}, [%4];"
                 : "=r"(r[0]), "=r"(r[1]), "=r"(r[2]), "=r"(r[3]) : "r"(a));
}
__device__ __forceinline__ void mma16(float& d0, float& d1, float& d2, float& d3,
                                      uint32_t a0, uint32_t a1, uint32_t a2, uint32_t a3,
                                      uint32_t b0, uint32_t b1) {
    asm volatile(
        "mma.sync.aligned.m16n8k16.row.col.f32.f16.f16.f32 "
        "{%0,%1,%2,%3},{%4,%5,%6,%7},{%8,%9},{%0,%1,%2,%3};"
        : "+f"(d0), "+f"(d1), "+f"(d2), "+f"(d3)
        : "r"(a0), "r"(a1), "r"(a2), "r"(a3), "r"(b0), "r"(b1));
}

// ===========================================================================
// cvt: H (fp32 -> f16 exact) and X (fp32 -> f16 rn) streaming conversion
// ===========================================================================
__global__ void __launch_bounds__(256)
cvt_kernel(const float* __restrict__ H, const float* __restrict__ X) {
    const size_t NH4 = (size_t)BB * NN * EE / 4;
    const size_t NX4 = (size_t)BB * NN * CC / 4;
    size_t i = (size_t)blockIdx.x * blockDim.x + threadIdx.x;
    const size_t stride = (size_t)gridDim.x * blockDim.x;
    for (; i < NH4 + NX4; i += stride) {
        if (i < NH4) {
            float4 f = reinterpret_cast<const float4*>(H)[i];
            reinterpret_cast<uint2*>(g_Hh)[i] = make_uint2(pk(f.x, f.y), pk(f.z, f.w));
        } else {
            size_t j = i - NH4;
            float4 f = reinterpret_cast<const float4*>(X)[j];
            reinterpret_cast<uint2*>(g_Xh)[j] = make_uint2(pk(f.x, f.y), pk(f.z, f.w));
        }
    }
}

// ===========================================================================
// S1 (+fused projection):
//   D1[e][c] = sum_n H[n][e] * X[n][c]     (A=H^T via ldmatrix.trans, cp.async feed)
//   se[e]    = ones-column MMA row-sum     (exact, f32 accum)
//   E[e][c'] = se>0 ? (D1/se) @ W + b : 0  -> g_E (f16)
// ===========================================================================
__global__ void __launch_bounds__(NTH, 2)
s1_kernel(const float* __restrict__ Wm, const float* __restrict__ bias) {
    const int b = blockIdx.y, e0 = blockIdx.x * BM;
    extern __shared__ __half sm[];
    __half* As = sm;                        // NSTG bufs [32][LKM]  (Hh tile [n][e])
    __half* Bs = sm + NSTG * 32 * LKM;      // NSTG bufs [32][LKM]  (Xh tile [n][c])
    __half* zsm = sm;                       // epilogue overlay [128][LDZ]
    __half* wsm = sm + BM * LDZ;
    __shared__ float s_rs[BM], s_inv[BM], s_b[CC];

    const int tid = threadIdx.x, lane = tid & 31, wid = tid >> 5;
    const int g = lane >> 2, tg = lane & 3;
    const int wm = (wid >> 2) * 64, wn = (wid & 3) * 32;   // 2x4 warps, 64x32 tiles
    const int t7 = tid >> 7;
    const bool do_rs = ((wid & 3) == 0);
    const uint32_t bones = (lane < 4) ? 0x3C003C00u : 0u;  // B[:,0] = 1.0

    if (tid < CC) s_b[tid] = bias[tid];

    const uint32_t uA = smem_u32(As), uB = smem_u32(Bs);
    const uint32_t aoff = (uint32_t)(((lane & 7) + ((lane >> 4) & 1) * 8) * LKM_B
                                     + ((lane >> 3) & 1) * 16);
    const uint32_t boff = (uint32_t)((lane & 7) * LKM_B + (lane >> 3) * 16);

    const __half* Hh_b = g_Hh + (size_t)b * NN * EE + e0;
    const __half* Xh_b = g_Xh + (size_t)b * NN * CC;

    float acc[4][4][4];
#pragma unroll
    for (int i = 0; i < 4; i++)
#pragma unroll
        for (int j = 0; j < 4; j++)
#pragma unroll
            for (int k = 0; k < 4; k++) acc[i][j][k] = 0.f;
    float acc_s[4][4];
#pragma unroll
    for (int i = 0; i < 4; i++)
#pragma unroll
        for (int j = 0; j < 4; j++) acc_s[i][j] = 0.f;

    auto LOAD = [&](int s, int n0) {
#pragma unroll
        for (int i = 0; i < 2; i++) {
            const int c = tid + i * NTH;            // 0..511
            const int row = c >> 4, u = c & 15;
            cpa16(uA + s * KMSZ_B + row * LKM_B + u * 16,
                  Hh_b + (size_t)(n0 + row) * EE + u * 8);
            cpa16(uB + s * KMSZ_B + row * LKM_B + u * 16,
                  Xh_b + (size_t)(n0 + row) * CC + u * 8);
        }
    };
    auto COMPUTE = [&](int s) {
        const uint32_t aBp = uA + s * KMSZ_B + (uint32_t)(wm * 2) + aoff;
        const uint32_t bBp = uB + s * KMSZ_B + (uint32_t)(wn * 2) + boff;
#pragma unroll
        for (int kk = 0; kk < BK; kk += 16) {
            uint32_t af[4][4], b0[4], b1[4];
#pragma unroll
            for (int mt = 0; mt < 4; mt++)
                ldsm4t(af[mt], aBp + kk * LKM_B + mt * 32);
            ldsm4t(b0, bBp + kk * LKM_B);
            ldsm4t(b1, bBp + (kk + 8) * LKM_B);
#pragma unroll
            for (int mt = 0; mt < 4; mt++)
#pragma unroll
                for (int nt = 0; nt < 4; nt++)
                    mma16(acc[mt][nt][0], acc[mt][nt][1], acc[mt][nt][2], acc[mt][nt][3],
                          af[mt][0], af[mt][1], af[mt][2], af[mt][3],
                          b0[nt], b1[nt]);
            if (do_rs) {
#pragma unroll
                for (int mt = 0; mt < 4; mt++)
                    mma16(acc_s[mt][0], acc_s[mt][1], acc_s[mt][2], acc_s[mt][3],
                          af[mt][0], af[mt][1], af[mt][2], af[mt][3], bones, bones);
            }
        }
    };

    LOAD(0, 0); CP_COMMIT();
    LOAD(1, BK); CP_COMMIT();
    const int KT = NN / BK;   // 128
    for (int kt = 0; kt < KT; kt++) {
        CP_WAIT1();
        __syncthreads();
        if (kt + 2 < KT) LOAD((kt + 2) % NSTG, (kt + 2) * BK);
        CP_COMMIT();
        COMPUTE(kt % NSTG);
    }

    // se from ones-column (D col 0 of rowsum tile lives at tg==0: d0/row g, d2/row g+8)
    if (do_rs && tg == 0) {
#pragma unroll
        for (int mt = 0; mt < 4; mt++) {
            s_rs[wm + mt * 16 + g] = acc_s[mt][0];
            s_rs[wm + mt * 16 + 8 + g] = acc_s[mt][2];
        }
    }
    __syncthreads();
    if (tid < BM) s_inv[tid] = (s_rs[tid] > 0.f) ? (1.f / s_rs[tid]) : 0.f;
    __syncthreads();   // all warps past ldmatrix reads -> overlay safe

    // ---- zhat -> zsm[e][c] f16;  W -> wsm[c'][k=c] f16 ----
#pragma unroll
    for (int mt = 0; mt < 4; mt++) {
        const int r0 = wm + mt * 16 + g;
        const float i0 = s_inv[r0], i1 = s_inv[r0 + 8];
#pragma unroll
        for (int nt = 0; nt < 4; nt++) {
            const int c = wn + nt * 8 + 2 * tg;
            *(uint32_t*)(zsm + r0 * LDZ + c) = pk(acc[mt][nt][0] * i0, acc[mt][nt][1] * i0);
            *(uint32_t*)(zsm + (r0 + 8) * LDZ + c) = pk(acc[mt][nt][2] * i1, acc[mt][nt][3] * i1);
        }
    }
    {
        const int cp = tid & 127;
#pragma unroll
        for (int i = 0; i < 16; i++) {
            const int kq = t7 + 2 * i;
            const float* wp = Wm + (size_t)(4 * kq) * CC + cp;
            *reinterpret_cast<uint2*>(wsm + cp * LDZ + kq * 4) =
                make_uint2(pk(wp[0], wp[CC]), pk(wp[2 * CC], wp[3 * CC]));
        }
    }
    __syncthreads();

    // ---- projection: E[e][c'] = zhat @ W  (K=128) ----
    float ac2[4][4][4];
#pragma unroll
    for (int i = 0; i < 4; i++)
#pragma unroll
        for (int j = 0; j < 4; j++)
#pragma unroll
            for (int k = 0; k < 4; k++) ac2[i][j][k] = 0.f;
#pragma unroll
    for (int kk = 0; kk < CC; kk += 16) {
        uint32_t af[4][4], bf[4][2];
#pragma unroll
        for (int mt = 0; mt < 4; mt++) {
            const __half* ap = zsm + (wm + mt * 16 + g) * LDZ + kk + 2 * tg;
            af[mt][0] = *(const uint32_t*)ap;
            af[mt][1] = *(const uint32_t*)(ap + 8 * LDZ);
            af[mt][2] = *(const uint32_t*)(ap + 8);
            af[mt][3] = *(const uint32_t*)(ap + 8 * LDZ + 8);
        }
#pragma unroll
        for (int nt = 0; nt < 4; nt++) {
            const __half* bp = wsm + (wn + nt * 8 + g) * LDZ + kk + 2 * tg;
            bf[nt][0] = *(const uint32_t*)bp;
            bf[nt][1] = *(const uint32_t*)(bp + 8);
        }
#pragma unroll
        for (int mt = 0; mt < 4; mt++)
#pragma unroll
            for (int nt = 0; nt < 4; nt++)
                mma16(ac2[mt][nt][0], ac2[mt][nt][1], ac2[mt][nt][2], ac2[mt][nt][3],
                      af[mt][0], af[mt][1], af[mt][2], af[mt][3],
                      bf[nt][0], bf[nt][1]);
    }

    // ---- bias + guard + store E (f16) ----
#pragma unroll
    for (int mt = 0; mt < 4; mt++) {
        const int r0 = wm + mt * 16 + g;
        const bool ok0 = s_rs[r0] > 0.f;
        const bool ok1 = s_rs[r0 + 8] > 0.f;
        __half* ep0 = g_E + ((size_t)(b * EE + e0 + r0)) * CC;
        __half* ep1 = ep0 + (size_t)8 * CC;
#pragma unroll
        for (int nt = 0; nt < 4; nt++) {
            const int c = wn + nt * 8 + 2 * tg;
            const float b0v = s_b[c], b1v = s_b[c + 1];
            *(uint32_t*)(ep0 + c) = pk(ok0 ? ac2[mt][nt][0] + b0v : 0.f,
                                       ok0 ? ac2[mt][nt][1] + b1v : 0.f);
            *(uint32_t*)(ep1 + c) = pk(ok1 ? ac2[mt][nt][2] + b0v : 0.f,
                                       ok1 ? ac2[mt][nt][3] + b1v : 0.f);
        }
    }
}

// ===========================================================================
// S3: v[n][c] = (sum_e H[n][e] * E[e][c]) / sv[n]   (sv via ones-column MMA)
//   A = Hh [n][e] (ldmatrix non-trans), B = E [e][c] (ldmatrix.trans), cp.async
// ===========================================================================
__global__ void __launch_bounds__(NTH, 2)
s3_kernel(float* __restrict__ out) {
    const int b = blockIdx.y, n0 = blockIdx.x * BM;
    extern __shared__ __half sm[];
    __half* As = sm;                        // NSTG bufs [128][LDA3]
    __half* Bs = sm + NSTG * BM * LDA3;     // NSTG bufs [32][LKM]
    __shared__ float s_rs[BM], s_inv[BM];

    const int tid = threadIdx.x, lane = tid & 31, wid = tid >> 5;
    const int g = lane >> 2, tg = lane & 3;
    const int wm = (wid >> 2) * 64, wn = (wid & 3) * 32;
    const bool do_rs = ((wid & 3) == 0);
    const uint32_t bones = (lane < 4) ? 0x3C003C00u : 0u;

    const uint32_t uA = smem_u32(As), uB = smem_u32(Bs);
    const uint32_t aoffA = (uint32_t)(((lane & 7) + ((lane >> 3) & 1) * 8) * LDA3_B
                                      + ((lane >> 4) & 1) * 16);
    const uint32_t boff = (uint32_t)((lane & 7) * LKM_B + (lane >> 3) * 16);

    const __half* Hh_b = g_Hh + (size_t)b * NN * EE;
    const __half* Eb = g_E + (size_t)b * EE * CC;

    float acc[4][4][4];
#pragma unroll
    for (int i = 0; i < 4; i++)
#pragma unroll
        for (int j = 0; j < 4; j++)
#pragma unroll
            for (int k = 0; k < 4; k++) acc[i][j][k] = 0.f;
    float acc_s[4][4];
#pragma unroll
    for (int i = 0; i < 4; i++)
#pragma unroll
        for (int j = 0; j < 4; j++) acc_s[i][j] = 0.f;

    auto LOAD = [&](int s, int es) {
#pragma unroll
        for (int i = 0; i < 2; i++) {
            const int c = tid + i * NTH;            // 0..511
            const int arow = c >> 2, k16 = c & 3;
            cpa16(uA + s * ASZ3_B + arow * LDA3_B + k16 * 16,
                  Hh_b + (size_t)(n0 + arow) * EE + es + k16 * 8);
            const int brow = c >> 4, u = c & 15;
            cpa16(uB + s * KMSZ_B + brow * LKM_B + u * 16,
                  Eb + (size_t)(es + brow) * CC + u * 8);
        }
    };
    auto COMPUTE = [&](int s) {
        const uint32_t aBp = uA + s * ASZ3_B + (uint32_t)(wm * LDA3_B) + aoffA;
        const uint32_t bBp = uB + s * KMSZ_B + (uint32_t)(wn * 2) + boff;
#pragma unroll
        for (int kk = 0; kk < BK; kk += 16) {
            uint32_t af[4][4], b0[4], b1[4];
#pragma unroll
            for (int mt = 0; mt < 4; mt++)
                ldsm4(af[mt], aBp + mt * 16 * LDA3_B + kk * 2);
            ldsm4t(b0, bBp + kk * LKM_B);
            ldsm4t(b1, bBp + (kk + 8) * LKM_B);
#pragma unroll
            for (int mt = 0; mt < 4; mt++)
#pragma unroll
                for (int nt = 0; nt < 4; nt++)
                    mma16(acc[mt][nt][0], acc[mt][nt][1], acc[mt][nt][2], acc[mt][nt][3],
                          af[mt][0], af[mt][1], af[mt][2], af[mt][3],
                          b0[nt], b1[nt]);
            if (do_rs) {
#pragma unroll
                for (int mt = 0; mt < 4; mt++)
                    mma16(acc_s[mt][0], acc_s[mt][1], acc_s[mt][2], acc_s[mt][3],
                          af[mt][0], af[mt][1], af[mt][2], af[mt][3], bones, bones);
            }
        }
    };

    LOAD(0, 0); CP_COMMIT();
    LOAD(1, BK); CP_COMMIT();
    const int KT = EE / BK;   // 64
    for (int kt = 0; kt < KT; kt++) {
        CP_WAIT1();
        __syncthreads();
        if (kt + 2 < KT) LOAD((kt + 2) % NSTG, (kt + 2) * BK);
        CP_COMMIT();
        COMPUTE(kt % NSTG);
    }

    if (do_rs && tg == 0) {
#pragma unroll
        for (int mt = 0; mt < 4; mt++) {
            s_rs[wm + mt * 16 + g] = acc_s[mt][0];
            s_rs[wm + mt * 16 + 8 + g] = acc_s[mt][2];
        }
    }
    __syncthreads();
    if (tid < BM) s_inv[tid] = (s_rs[tid] > 0.f) ? (1.f / s_rs[tid]) : 0.f;
    __syncthreads();

#pragma unroll
    for (int mt = 0; mt < 4; mt++) {
        const int r0 = wm + mt * 16 + g;
        const float i0 = s_inv[r0], i1 = s_inv[r0 + 8];
        float* op0 = out + (size_t)(b * NN + n0 + r0) * CC;
        float* op1 = op0 + (size_t)8 * CC;
#pragma unroll
        for (int nt = 0; nt < 4; nt++) {
            const int c = wn + nt * 8 + 2 * tg;
            *reinterpret_cast<float2*>(op0 + c) =
                make_float2(acc[mt][nt][0] * i0, acc[mt][nt][1] * i0);
            *reinterpret_cast<float2*>(op1 + c) =
                make_float2(acc[mt][nt][2] * i1, acc[mt][nt][3] * i1);
        }
    }
}

// ===========================================================================
extern "C" void kernel_launch(void* const* d_in, const int* in_sizes, int n_in,
                              void* d_out, int out_size) {
    const float* X = nullptr;
    const float* H = nullptr;
    const float* W = nullptr;
    const float* bias = nullptr;
    for (int i = 0; i < n_in; i++) {
        if (in_sizes[i] == BB * NN * CC)      X = (const float*)d_in[i];
        else if (in_sizes[i] == BB * NN * EE) H = (const float*)d_in[i];
        else if (in_sizes[i] == CC * CC)      W = (const float*)d_in[i];
        else if (in_sizes[i] == CC)           bias = (const float*)d_in[i];
    }
    float* out = (float*)d_out;

    const int s1_main = NSTG * 2 * KMSZ_B;                      // 52224
    const int s1_epi  = 2 * BM * LDZ * (int)sizeof(__half);     // 69632
    const int smem1 = (s1_main > s1_epi) ? s1_main : s1_epi;
    const int smem3 = NSTG * (ASZ3_B + KMSZ_B);                 // 81408

    cudaFuncSetAttribute(s1_kernel, cudaFuncAttributeMaxDynamicSharedMemorySize, smem1);
    cudaFuncSetAttribute(s3_kernel, cudaFuncAttributeMaxDynamicSharedMemorySize, smem3);

    cvt_kernel<<<4736, 256>>>(H, X);
    s1_kernel<<<dim3(EE / BM, BB), NTH, smem1>>>(W, bias);
    s3_kernel<<<dim3(NN / BM, BB), NTH, smem3>>>(out);
}